// round 7
// baseline (speedup 1.0000x reference)
#include <cuda_runtime.h>
#include <cuda_bf16.h>

// Problem constants (fixed shapes for this bench)
#define B_   16
#define C_   256
#define H_   224
#define W_   224
#define P_   14
#define NH_  16
#define NW_  16
#define N_   256          // NH_*NW_ patches
#define CC_  4            // channels per tile (one per thread-group)
#define NCH_ 64           // C_/CC_
#define NTILE_ (NCH_ * B_ * NH_)   // 16384 logical tiles
#define NCTA_  1184                // 148 SMs x 8 resident CTAs
#define EPS_COS  1e-8f
#define EPS_NORM 1e-12f

// Scratch (every slot written every launch)
__device__ float g_dot[NCH_ * B_ * N_];   // [chunk][b][n]
__device__ float g_nsq[NCH_ * B_ * N_];   // [chunk][b][n]
__device__ float g_qsq[NCH_ * B_];        // [chunk][b]
__device__ float g_loss[B_];
__device__ int   g_ticket = 0;            // reset by finalizeB for next replay

// ---------------------------------------------------------------------------
// Kernel 1 (persistent): ticket-scheduled tiles (chunk, b, ph).
// 224 threads = 4 channel-groups x 56 float4-columns. Each thread streams
// one channel x 14 rows of float4 (LDG.128, fully aligned, coalesced).
// ---------------------------------------------------------------------------
__global__ __launch_bounds__(224, 8)
void accum_kernel(const float* __restrict__ qf,
                  const float* __restrict__ rf,
                  const int*   __restrict__ click) {
    __shared__ float smq[CC_ * P_ * P_];   // 784 floats  [cc][i][j]
    __shared__ float sdot[CC_ * 224];      // per-(z,col) dot partials
    __shared__ float snsq[CC_ * 224];      // per-(z,col) nsq partials
    __shared__ int   s_tile;

    const int tid  = threadIdx.x;          // 0..223
    const int z    = tid / 56;             // channel group == channel index
    const int w4   = tid - z * 56;         // float4 column
    const int col0 = 4 * w4;
    // per-element within-patch column index (fixed per thread)
    const int j0 = (col0 + 0) % P_;
    const int j1 = (col0 + 1) % P_;
    const int j2 = (col0 + 2) % P_;
    const int j3 = (col0 + 3) % P_;

    for (;;) {
        __syncthreads();                   // protect s_tile/smem from prev iter
        if (tid == 0) s_tile = atomicAdd(&g_ticket, 1);
        __syncthreads();
        const int t = s_tile;
        if (t >= NTILE_) break;

        // decode: t = ((chunk*B_) + b)*NH_ + ph
        const int chunk = t >> 8;
        const int b     = (t >> 4) & 15;
        const int ph    = t & 15;
        const int c0    = chunk * CC_;

        const int qx = click[2 * b + 0];
        const int qy = click[2 * b + 1];
        const int qh = qy / P_;
        const int qw = qx / P_;

        // Stage query patch tile (4 channels x 14 x 14)
        const float* qbase = qf + ((size_t)(b * C_ + c0) * H_ + qh * P_) * W_ + qw * P_;
        for (int idx = tid; idx < CC_ * P_ * P_; idx += 224) {
            int cc = idx / (P_ * P_);
            int r  = idx - cc * (P_ * P_);
            int i  = r / P_;
            int j  = r - i * P_;
            smq[idx] = qbase[(cc * H_ + i) * W_ + j];
        }
        __syncthreads();

        // Stream: one channel (z), 14 rows of float4 per thread
        {
            const float4* tp = (const float4*)(rf +
                ((size_t)(b * C_ + c0 + z) * H_ + ph * P_) * W_) + w4;
            const float* qp = smq + z * (P_ * P_);

            float d0 = 0.f, d1 = 0.f, d2 = 0.f, d3 = 0.f;
            float s0 = 0.f, s1 = 0.f, s2 = 0.f, s3 = 0.f;
#pragma unroll
            for (int i = 0; i < P_; ++i) {
                float4 v = __ldcs(tp + i * (W_ / 4));
                const float* q = qp + i * P_;
                d0 = fmaf(v.x, q[j0], d0);  s0 = fmaf(v.x, v.x, s0);
                d1 = fmaf(v.y, q[j1], d1);  s1 = fmaf(v.y, v.y, s1);
                d2 = fmaf(v.z, q[j2], d2);  s2 = fmaf(v.z, v.z, s2);
                d3 = fmaf(v.w, q[j3], d3);  s3 = fmaf(v.w, v.w, s3);
            }
            *(float4*)(sdot + z * 224 + col0) = make_float4(d0, d1, d2, d3);
            *(float4*)(snsq + z * 224 + col0) = make_float4(s0, s1, s2, s3);
        }
        __syncthreads();

        // Reduce over channels (4) and 14 columns -> one patch each
        if (tid < NW_) {
            float d = 0.f, s = 0.f;
#pragma unroll
            for (int zz = 0; zz < CC_; ++zz) {
#pragma unroll
                for (int k = 0; k < P_; ++k) {
                    d += sdot[zz * 224 + tid * P_ + k];
                    s += snsq[zz * 224 + tid * P_ + k];
                }
            }
            const int n = ph * NW_ + tid;
            g_dot[(chunk * B_ + b) * N_ + n] = d;
            g_nsq[(chunk * B_ + b) * N_ + n] = s;
        }

        // ph==0 tiles also compute partial ||q||^2 (warp shuffle reduce)
        if (ph == 0) {
            float acc = 0.f;
            for (int idx = tid; idx < CC_ * P_ * P_; idx += 224) {
                float v = smq[idx];
                acc = fmaf(v, v, acc);
            }
#pragma unroll
            for (int o = 16; o > 0; o >>= 1)
                acc += __shfl_down_sync(0xffffffffu, acc, o);
            __syncthreads();               // sdot readers above are done
            if ((tid & 31) == 0) sdot[tid >> 5] = acc;
            __syncthreads();
            if (tid == 0) {
                float s = 0.f;
#pragma unroll
                for (int k = 0; k < 7; ++k) s += sdot[k];
                g_qsq[chunk * B_ + b] = s;
            }
        }
    }
}

// ---------------------------------------------------------------------------
// Kernel 2: per-batch cosine-sim -> normalize -> log-softmax -> loss_b
// ---------------------------------------------------------------------------
__global__ __launch_bounds__(256)
void finalizeA_kernel(const float* __restrict__ logit_scale,
                      const int*   __restrict__ gt) {
    const int b   = blockIdx.x;
    const int tid = threadIdx.x;
    __shared__ float sh[256];

    // ||q||^2 = sum of chunk partials
    sh[tid] = (tid < NCH_) ? g_qsq[tid * B_ + b] : 0.f;
    __syncthreads();
    for (int s = 128; s > 0; s >>= 1) {
        if (tid < s) sh[tid] += sh[tid + s];
        __syncthreads();
    }
    const float Qc = fmaxf(sqrtf(sh[0]), EPS_COS);
    __syncthreads();

    // Per-patch (n == tid) sums across chunks
    const int n = tid;
    float dot = 0.f, tsq = 0.f;
#pragma unroll 8
    for (int ch = 0; ch < NCH_; ++ch) {
        dot += g_dot[(ch * B_ + b) * N_ + n];
        tsq += g_nsq[(ch * B_ + b) * N_ + n];
    }
    float s_n = dot / (fmaxf(sqrtf(tsq), EPS_COS) * Qc);

    // F.normalize over the 256-wide sim vector
    sh[tid] = s_n * s_n;
    __syncthreads();
    for (int s = 128; s > 0; s >>= 1) {
        if (tid < s) sh[tid] += sh[tid + s];
        __syncthreads();
    }
    const float r = fmaxf(sqrtf(sh[0]), EPS_NORM);
    __syncthreads();

    const float l = logit_scale[0] * (s_n / r);

    // log-softmax: max
    sh[tid] = l;
    __syncthreads();
    for (int s = 128; s > 0; s >>= 1) {
        if (tid < s) sh[tid] = fmaxf(sh[tid], sh[tid + s]);
        __syncthreads();
    }
    const float m = sh[0];
    __syncthreads();

    // sum exp
    sh[tid] = __expf(l - m);
    __syncthreads();
    for (int s = 128; s > 0; s >>= 1) {
        if (tid < s) sh[tid] += sh[tid + s];
        __syncthreads();
    }
    const float lse = m + logf(sh[0]);

    const int gx = gt[2 * b + 0];
    const int gy = gt[2 * b + 1];
    const int label = (gy / P_) * NW_ + (gx / P_);
    if (n == label) g_loss[b] = lse - l;   // -logp[label]
}

// ---------------------------------------------------------------------------
// Kernel 3: mean over batches + reset ticket for next graph replay
// ---------------------------------------------------------------------------
__global__ void finalizeB_kernel(float* __restrict__ out) {
    if (threadIdx.x == 0) {
        float acc = 0.f;
        for (int b = 0; b < B_; ++b) acc += g_loss[b];
        out[0] = acc / (float)B_;
        g_ticket = 0;                      // reset scheduler for next replay
    }
}

// ---------------------------------------------------------------------------
extern "C" void kernel_launch(void* const* d_in, const int* in_sizes, int n_in,
                              void* d_out, int out_size) {
    const float* qf    = (const float*)d_in[0];   // query_feature [16,256,224,224]
    const float* rf    = (const float*)d_in[1];   // ref_feature   [16,256,224,224]
    const float* scale = (const float*)d_in[2];   // logit_scale scalar
    const int*   click = (const int*)  d_in[3];   // click_points [16,2] int32
    const int*   gt    = (const int*)  d_in[4];   // gt_points    [16,2] int32
    // d_in[5] = patch_size (14), fixed -> hardcoded

    accum_kernel<<<NCTA_, 224>>>(qf, rf, click);
    finalizeA_kernel<<<B_, 256>>>(scale, gt);
    finalizeB_kernel<<<1, 32>>>((float*)d_out);
}

// round 8
// speedup vs baseline: 1.1031x; 1.1031x over previous
#include <cuda_runtime.h>
#include <cuda_bf16.h>

// Problem constants (fixed shapes for this bench)
#define B_   16
#define C_   256
#define H_   224
#define W_   224
#define P_   14
#define NH_  16
#define NW_  16
#define N_   256          // NH_*NW_ patches
#define CC_  4            // channels per tile
#define NCH_ 64           // C_/CC_
#define NTILE_ (NCH_ * B_ * NH_)   // 16384 logical tiles
#define NCTA_  1332                // 148 SMs x 9 resident CTAs
#define QSZ_  (CC_ * P_ * P_)      // 784 floats per q tile
#define EPS_COS  1e-8f
#define EPS_NORM 1e-12f

// Scratch (every consumed slot written every launch)
__device__ float g_dot[NCH_ * B_ * N_];   // [chunk][b][n]
__device__ float g_nsq[NCH_ * B_ * N_];   // [chunk][b][n]
__device__ float g_qsq[NCH_ * B_];        // [chunk][b]
__device__ float g_loss[B_];
__device__ int   g_ticket = 0;            // reset by last finalize block
__device__ int   g_done   = 0;            // reset by last finalize block

// ---------------------------------------------------------------------------
// Kernel 1 (persistent, software-pipelined): ticket tiles (chunk, b, ph).
// 224 threads = 7 warps, all streaming scalar loads (56 per thread per tile).
// Next ticket fetched during streaming; next q-tile staged during reduce.
// ---------------------------------------------------------------------------
__device__ __forceinline__ void stage_q(const float* __restrict__ qf,
                                        const int*   __restrict__ click,
                                        int t, float* __restrict__ dstq,
                                        int tid) {
    const int chunk = t >> 8;
    const int b     = (t >> 4) & 15;
    const int c0    = chunk * CC_;
    const int qh    = click[2 * b + 1] / P_;
    const int qw    = click[2 * b + 0] / P_;
    const float* qbase = qf + ((size_t)(b * C_ + c0) * H_ + qh * P_) * W_ + qw * P_;
#pragma unroll
    for (int k = 0; k < 4; ++k) {          // 784 = 3*224 + 112
        int idx = tid + k * 224;
        if (idx < QSZ_) {
            int cc = idx / (P_ * P_);
            int r  = idx - cc * (P_ * P_);
            int i  = r / P_;
            int j  = r - i * P_;
            dstq[idx] = qbase[(cc * H_ + i) * W_ + j];
        }
    }
}

__global__ __launch_bounds__(224, 9)
void accum_kernel(const float* __restrict__ qf,
                  const float* __restrict__ rf,
                  const int*   __restrict__ click) {
    __shared__ float smq[2][QSZ_];         // double-buffered q tile
    __shared__ float sred[2 * 224];        // column partials (dot | nsq)
    __shared__ float sqs[8];               // qsq warp-leader partials
    __shared__ int   s_tile[2];

    const int tid = threadIdx.x;           // 0..223
    const int w   = tid;
    const int pw  = w / P_;
    const int j   = w - pw * P_;           // within-patch column (fixed)

    // Prologue: first ticket + first q-tile stage
    if (tid == 0) s_tile[0] = atomicAdd(&g_ticket, 1);
    __syncthreads();
    int buf = 0;
    int t   = s_tile[0];
    if (t < NTILE_) stage_q(qf, click, t, smq[0], tid);
    __syncthreads();

    while (t < NTILE_) {
        const int nbuf = buf ^ 1;
        // Fetch next ticket early; latency hides behind streaming loads
        if (tid == 0) s_tile[nbuf] = atomicAdd(&g_ticket, 1);

        const int chunk = t >> 8;
        const int b     = (t >> 4) & 15;
        const int ph    = t & 15;
        const int c0    = chunk * CC_;

        // Stream ref rows: one column per thread, 128B/warp coalesced
        {
            const float* tbase = rf + ((size_t)(b * C_ + c0) * H_ + ph * P_) * W_ + w;
            const float* qsm   = smq[buf];
            float dot = 0.f, nsq = 0.f;
#pragma unroll
            for (int cc = 0; cc < CC_; ++cc) {
                const float* tp = tbase + cc * (H_ * W_);
                const float* qp = qsm + cc * (P_ * P_) + j;
#pragma unroll
                for (int i = 0; i < P_; ++i) {
                    float tv = __ldcs(tp + i * W_);   // streaming, evict-first
                    float qv = qp[i * P_];
                    dot = fmaf(tv, qv, dot);
                    nsq = fmaf(tv, tv, nsq);
                }
            }
            sred[w]       = dot;
            sred[224 + w] = nsq;
        }
        __syncthreads();                   // sred ready; s_tile[nbuf] visible

        const int t_next = s_tile[nbuf];
        // Stage next q-tile (overlaps the reductions below)
        if (t_next < NTILE_) stage_q(qf, click, t_next, smq[nbuf], tid);

        // Reduce 14 columns -> one patch; disjoint slots, no atomics
        if (tid < NW_) {
            float d = 0.f, s = 0.f;
#pragma unroll
            for (int k = 0; k < P_; ++k) {
                d += sred[tid * P_ + k];
                s += sred[224 + tid * P_ + k];
            }
            const int n = ph * NW_ + tid;
            g_dot[(chunk * B_ + b) * N_ + n] = d;
            g_nsq[(chunk * B_ + b) * N_ + n] = s;
        }

        // ph==0 tiles also compute partial ||q||^2 from current q tile
        if (ph == 0) {
            float acc = 0.f;
#pragma unroll
            for (int k = 0; k < 4; ++k) {
                int idx = tid + k * 224;
                if (idx < QSZ_) {
                    float v = smq[buf][idx];
                    acc = fmaf(v, v, acc);
                }
            }
#pragma unroll
            for (int o = 16; o > 0; o >>= 1)
                acc += __shfl_down_sync(0xffffffffu, acc, o);
            if ((tid & 31) == 0) sqs[tid >> 5] = acc;
        }
        __syncthreads();                   // staging done; sqs visible; sred free
        if (ph == 0 && tid == 0) {
            float s = 0.f;
#pragma unroll
            for (int k = 0; k < 7; ++k) s += sqs[k];
            g_qsq[chunk * B_ + b] = s;     // safe: sqs rewritten only after next mid-barrier
        }

        buf = nbuf;
        t   = t_next;
    }
}

// ---------------------------------------------------------------------------
// Kernel 2: per-batch cosine-sim -> normalize -> log-softmax -> loss_b,
// with last-block mean into d_out (finalizeB fused).
// ---------------------------------------------------------------------------
__global__ __launch_bounds__(256)
void finalize_kernel(const float* __restrict__ logit_scale,
                     const int*   __restrict__ gt,
                     float* __restrict__ out) {
    const int b   = blockIdx.x;
    const int tid = threadIdx.x;
    __shared__ float sh[256];
    __shared__ int   s_rank;

    // ||q||^2 = sum of chunk partials
    sh[tid] = (tid < NCH_) ? g_qsq[tid * B_ + b] : 0.f;
    __syncthreads();
    for (int s = 128; s > 0; s >>= 1) {
        if (tid < s) sh[tid] += sh[tid + s];
        __syncthreads();
    }
    const float Qc = fmaxf(sqrtf(sh[0]), EPS_COS);
    __syncthreads();

    // Per-patch (n == tid) sums across chunks
    const int n = tid;
    float dot = 0.f, tsq = 0.f;
#pragma unroll 8
    for (int ch = 0; ch < NCH_; ++ch) {
        dot += g_dot[(ch * B_ + b) * N_ + n];
        tsq += g_nsq[(ch * B_ + b) * N_ + n];
    }
    float s_n = dot / (fmaxf(sqrtf(tsq), EPS_COS) * Qc);

    // F.normalize over the 256-wide sim vector
    sh[tid] = s_n * s_n;
    __syncthreads();
    for (int s = 128; s > 0; s >>= 1) {
        if (tid < s) sh[tid] += sh[tid + s];
        __syncthreads();
    }
    const float r = fmaxf(sqrtf(sh[0]), EPS_NORM);
    __syncthreads();

    const float l = logit_scale[0] * (s_n / r);

    // log-softmax: max
    sh[tid] = l;
    __syncthreads();
    for (int s = 128; s > 0; s >>= 1) {
        if (tid < s) sh[tid] = fmaxf(sh[tid], sh[tid + s]);
        __syncthreads();
    }
    const float m = sh[0];
    __syncthreads();

    // sum exp
    sh[tid] = __expf(l - m);
    __syncthreads();
    for (int s = 128; s > 0; s >>= 1) {
        if (tid < s) sh[tid] += sh[tid + s];
        __syncthreads();
    }
    const float lse = m + logf(sh[0]);

    const int gx = gt[2 * b + 0];
    const int gy = gt[2 * b + 1];
    const int label = (gy / P_) * NW_ + (gx / P_);
    if (n == label) g_loss[b] = lse - l;   // -logp[label]

    // Last block computes the mean and resets scheduler state
    __syncthreads();
    __threadfence();
    if (tid == 0) s_rank = atomicAdd(&g_done, 1);
    __syncthreads();
    if (s_rank == B_ - 1 && tid == 0) {
        __threadfence();
        float acc = 0.f;
#pragma unroll
        for (int k = 0; k < B_; ++k) acc += g_loss[k];
        out[0]   = acc / (float)B_;
        g_ticket = 0;                      // reset for next graph replay
        g_done   = 0;
    }
}

// ---------------------------------------------------------------------------
extern "C" void kernel_launch(void* const* d_in, const int* in_sizes, int n_in,
                              void* d_out, int out_size) {
    const float* qf    = (const float*)d_in[0];   // query_feature [16,256,224,224]
    const float* rf    = (const float*)d_in[1];   // ref_feature   [16,256,224,224]
    const float* scale = (const float*)d_in[2];   // logit_scale scalar
    const int*   click = (const int*)  d_in[3];   // click_points [16,2] int32
    const int*   gt    = (const int*)  d_in[4];   // gt_points    [16,2] int32
    // d_in[5] = patch_size (14), fixed -> hardcoded

    accum_kernel<<<NCTA_, 224>>>(qf, rf, click);
    finalize_kernel<<<B_, 256>>>(scale, gt, (float*)d_out);
}

// round 9
// speedup vs baseline: 1.1244x; 1.0194x over previous
#include <cuda_runtime.h>
#include <cuda_bf16.h>

// Problem constants (fixed shapes for this bench)
#define B_   16
#define C_   256
#define H_   224
#define W_   224
#define P_   14
#define NH_  16
#define NW_  16
#define N_   256          // NH_*NW_ patches
#define CC_  4            // channels per tile
#define NCH_ 64           // C_/CC_
#define NTILE_ (NCH_ * B_ * NH_)   // 16384 logical tiles
#define NCTA_  1332                // 148 SMs x 9 resident CTAs
#define QSZ_  (CC_ * P_ * P_)      // 784 floats per q tile
#define EPS_COS  1e-8f
#define EPS_NORM 1e-12f

// Scratch (every consumed slot written every launch)
__device__ float g_dot[NCH_ * B_ * N_];   // [chunk][b][n]
__device__ float g_nsq[NCH_ * B_ * N_];   // [chunk][b][n]
__device__ float g_qsq[NCH_ * B_];        // [chunk][b]
__device__ float g_loss[B_];
__device__ int   g_ticket = 0;            // reset by finalizeB for next replay

// ---------------------------------------------------------------------------
// Kernel 1 (persistent): ticket tiles (chunk, b, ph). 224 threads = 7 warps,
// all streaming scalar loads (56 per thread per tile). The NEXT ticket is
// fetched at the start of the streaming phase so the ATOMG latency hides
// behind the 56-load stream instead of sitting serially between barriers.
// ---------------------------------------------------------------------------
__global__ __launch_bounds__(224)
void accum_kernel(const float* __restrict__ qf,
                  const float* __restrict__ rf,
                  const int*   __restrict__ click) {
    __shared__ float smq[QSZ_];            // q tile (single buffer)
    __shared__ float sred[2 * 224];        // column partials (dot | nsq)
    __shared__ float sqs[8];               // qsq warp-leader partials
    __shared__ int   s_tile[2];            // ticket double-slot

    const int tid = threadIdx.x;           // 0..223
    const int w   = tid;
    const int pw  = w / P_;
    const int j   = w - pw * P_;           // within-patch column (fixed)

    // Prologue: first ticket
    if (tid == 0) s_tile[0] = atomicAdd(&g_ticket, 1);
    __syncthreads();
    int t  = s_tile[0];
    int np = 1;                            // slot for the next ticket

    while (t < NTILE_) {
        const int chunk = t >> 8;
        const int b     = (t >> 4) & 15;
        const int ph    = t & 15;
        const int c0    = chunk * CC_;

        // Stage query patch tile (4 channels x 14 x 14) into smem
        {
            const int qh = click[2 * b + 1] / P_;
            const int qw = click[2 * b + 0] / P_;
            const float* qbase = qf + ((size_t)(b * C_ + c0) * H_ + qh * P_) * W_ + qw * P_;
            for (int idx = tid; idx < QSZ_; idx += 224) {
                int cc = idx / (P_ * P_);
                int r  = idx - cc * (P_ * P_);
                int i  = r / P_;
                int jj = r - i * P_;
                smq[idx] = qbase[(cc * H_ + i) * W_ + jj];
            }
        }
        __syncthreads();                   // smq ready

        // Prefetch next ticket; latency hides behind the streaming loads
        if (tid == 0) s_tile[np] = atomicAdd(&g_ticket, 1);

        // Stream ref rows: one column per thread, 128B/warp coalesced
        {
            const float* tbase = rf + ((size_t)(b * C_ + c0) * H_ + ph * P_) * W_ + w;
            float dot = 0.f, nsq = 0.f;
#pragma unroll
            for (int cc = 0; cc < CC_; ++cc) {
                const float* tp = tbase + cc * (H_ * W_);
                const float* qp = smq + cc * (P_ * P_) + j;
#pragma unroll
                for (int i = 0; i < P_; ++i) {
                    float tv = __ldcs(tp + i * W_);   // streaming, evict-first
                    float qv = qp[i * P_];
                    dot = fmaf(tv, qv, dot);
                    nsq = fmaf(tv, tv, nsq);
                }
            }
            sred[w]       = dot;
            sred[224 + w] = nsq;
        }
        __syncthreads();                   // sred ready; s_tile[np] visible

        // Reduce 14 columns -> one patch; disjoint slots, no atomics
        if (tid < NW_) {
            float d = 0.f, s = 0.f;
#pragma unroll
            for (int k = 0; k < P_; ++k) {
                d += sred[tid * P_ + k];
                s += sred[224 + tid * P_ + k];
            }
            const int n = ph * NW_ + tid;
            g_dot[(chunk * B_ + b) * N_ + n] = d;
            g_nsq[(chunk * B_ + b) * N_ + n] = s;
        }

        // ph==0 tiles also compute partial ||q||^2 (warp shuffle reduce)
        if (ph == 0) {
            float acc = 0.f;
            for (int idx = tid; idx < QSZ_; idx += 224) {
                float v = smq[idx];
                acc = fmaf(v, v, acc);
            }
#pragma unroll
            for (int o = 16; o > 0; o >>= 1)
                acc += __shfl_down_sync(0xffffffffu, acc, o);
            if ((tid & 31) == 0) sqs[tid >> 5] = acc;
        }
        __syncthreads();                   // sqs visible; smq free for next stage

        if (ph == 0 && tid == 0) {
            float s = 0.f;
#pragma unroll
            for (int k = 0; k < 7; ++k) s += sqs[k];
            g_qsq[chunk * B_ + b] = s;     // sqs next rewritten only after 2 more barriers
        }

        t  = s_tile[np];
        np ^= 1;
    }
}

// ---------------------------------------------------------------------------
// Kernel 2: per-batch cosine-sim -> normalize -> log-softmax -> loss_b
// ---------------------------------------------------------------------------
__global__ __launch_bounds__(256)
void finalizeA_kernel(const float* __restrict__ logit_scale,
                      const int*   __restrict__ gt) {
    const int b   = blockIdx.x;
    const int tid = threadIdx.x;
    __shared__ float sh[256];

    // ||q||^2 = sum of chunk partials
    sh[tid] = (tid < NCH_) ? g_qsq[tid * B_ + b] : 0.f;
    __syncthreads();
    for (int s = 128; s > 0; s >>= 1) {
        if (tid < s) sh[tid] += sh[tid + s];
        __syncthreads();
    }
    const float Qc = fmaxf(sqrtf(sh[0]), EPS_COS);
    __syncthreads();

    // Per-patch (n == tid) sums across chunks
    const int n = tid;
    float dot = 0.f, tsq = 0.f;
#pragma unroll 8
    for (int ch = 0; ch < NCH_; ++ch) {
        dot += g_dot[(ch * B_ + b) * N_ + n];
        tsq += g_nsq[(ch * B_ + b) * N_ + n];
    }
    float s_n = dot / (fmaxf(sqrtf(tsq), EPS_COS) * Qc);

    // F.normalize over the 256-wide sim vector
    sh[tid] = s_n * s_n;
    __syncthreads();
    for (int s = 128; s > 0; s >>= 1) {
        if (tid < s) sh[tid] += sh[tid + s];
        __syncthreads();
    }
    const float r = fmaxf(sqrtf(sh[0]), EPS_NORM);
    __syncthreads();

    const float l = logit_scale[0] * (s_n / r);

    // log-softmax: max
    sh[tid] = l;
    __syncthreads();
    for (int s = 128; s > 0; s >>= 1) {
        if (tid < s) sh[tid] = fmaxf(sh[tid], sh[tid + s]);
        __syncthreads();
    }
    const float m = sh[0];
    __syncthreads();

    // sum exp
    sh[tid] = __expf(l - m);
    __syncthreads();
    for (int s = 128; s > 0; s >>= 1) {
        if (tid < s) sh[tid] += sh[tid + s];
        __syncthreads();
    }
    const float lse = m + logf(sh[0]);

    const int gx = gt[2 * b + 0];
    const int gy = gt[2 * b + 1];
    const int label = (gy / P_) * NW_ + (gx / P_);
    if (n == label) g_loss[b] = lse - l;   // -logp[label]
}

// ---------------------------------------------------------------------------
// Kernel 3: mean over batches + reset ticket for next graph replay
// ---------------------------------------------------------------------------
__global__ void finalizeB_kernel(float* __restrict__ out) {
    if (threadIdx.x == 0) {
        float acc = 0.f;
        for (int b = 0; b < B_; ++b) acc += g_loss[b];
        out[0] = acc / (float)B_;
        g_ticket = 0;                      // reset scheduler for next replay
    }
}

// ---------------------------------------------------------------------------
extern "C" void kernel_launch(void* const* d_in, const int* in_sizes, int n_in,
                              void* d_out, int out_size) {
    const float* qf    = (const float*)d_in[0];   // query_feature [16,256,224,224]
    const float* rf    = (const float*)d_in[1];   // ref_feature   [16,256,224,224]
    const float* scale = (const float*)d_in[2];   // logit_scale scalar
    const int*   click = (const int*)  d_in[3];   // click_points [16,2] int32
    const int*   gt    = (const int*)  d_in[4];   // gt_points    [16,2] int32
    // d_in[5] = patch_size (14), fixed -> hardcoded

    accum_kernel<<<NCTA_, 224>>>(qf, rf, click);
    finalizeA_kernel<<<B_, 256>>>(scale, gt);
    finalizeB_kernel<<<1, 32>>>((float*)d_out);
}

// round 10
// speedup vs baseline: 1.1431x; 1.0166x over previous
#include <cuda_runtime.h>
#include <cuda_bf16.h>

// Problem constants (fixed shapes for this bench)
#define B_   16
#define C_   256
#define H_   224
#define W_   224
#define P_   14
#define NH_  16
#define NW_  16
#define N_   256          // NH_*NW_ patches
#define CC_  4            // channels per tile
#define NCH_ 64           // C_/CC_
#define NTILE_ (NCH_ * B_ * NH_)   // 16384 logical tiles
#define NCTA_  1332                // 148 SMs x 9 resident CTAs
#define QSZ_  (CC_ * P_ * P_)      // 784 floats per q tile
#define EPS_COS  1e-8f
#define EPS_NORM 1e-12f

// Scratch (every consumed slot written every launch)
__device__ float g_dot[NCH_ * B_ * N_];   // [chunk][b][n]
__device__ float g_nsq[NCH_ * B_ * N_];   // [chunk][b][n]
__device__ float g_qsq[NCH_ * B_];        // [chunk][b]
__device__ float g_loss[B_];
__device__ int   g_ticket = 0;            // reset by finalize's last block
__device__ int   g_done   = 0;            // reset by finalize's last block

// ---------------------------------------------------------------------------
// Kernel 1 (persistent): ticket-scheduled tiles (chunk, b, ph).
// 224 threads = 7 warps, all streaming. Each thread owns one image column.
// (R6 structure verbatim — best validated accum: 130.5us @ 80.9% DRAM.)
// ---------------------------------------------------------------------------
__global__ __launch_bounds__(224)
void accum_kernel(const float* __restrict__ qf,
                  const float* __restrict__ rf,
                  const int*   __restrict__ click) {
    __shared__ float smq[QSZ_];            // 784 floats
    __shared__ float sred[2 * 224];
    __shared__ int   s_tile;

    const int tid = threadIdx.x;           // 0..223

    for (;;) {
        __syncthreads();                   // protect s_tile/smq from prev iter
        if (tid == 0) s_tile = atomicAdd(&g_ticket, 1);
        __syncthreads();
        const int t = s_tile;
        if (t >= NTILE_) break;

        // decode: t = ((chunk*B_) + b)*NH_ + ph
        const int chunk = t >> 8;
        const int b     = (t >> 4) & 15;
        const int ph    = t & 15;
        const int c0    = chunk * CC_;

        const int qx = click[2 * b + 0];
        const int qy = click[2 * b + 1];
        const int qh = qy / P_;
        const int qw = qx / P_;

        // Stage query patch tile (CC_ x 14 x 14)
        const float* qbase = qf + ((size_t)(b * C_ + c0) * H_ + qh * P_) * W_ + qw * P_;
        for (int idx = tid; idx < QSZ_; idx += 224) {
            int cc = idx / (P_ * P_);
            int r  = idx - cc * (P_ * P_);
            int i  = r / P_;
            int j  = r - i * P_;
            smq[idx] = qbase[(cc * H_ + i) * W_ + j];
        }
        __syncthreads();

        // Stream ref rows: one column per thread, 128B/warp coalesced
        {
            const int w  = tid;
            const int pw = w / P_;
            const int j  = w - pw * P_;
            const float* tbase = rf + ((size_t)(b * C_ + c0) * H_ + ph * P_) * W_ + w;
            float dot = 0.f, nsq = 0.f;
#pragma unroll
            for (int cc = 0; cc < CC_; ++cc) {
                const float* tp = tbase + cc * (H_ * W_);
                const float* qp = smq + cc * (P_ * P_) + j;
#pragma unroll
                for (int i = 0; i < P_; ++i) {
                    float tv = __ldcs(tp + i * W_);   // streaming, evict-first
                    float qv = qp[i * P_];
                    dot = fmaf(tv, qv, dot);
                    nsq = fmaf(tv, tv, nsq);
                }
            }
            sred[w]       = dot;
            sred[224 + w] = nsq;
        }
        __syncthreads();

        // Reduce 14 columns -> one patch; disjoint slots, no atomics
        if (tid < NW_) {
            float d = 0.f, s = 0.f;
#pragma unroll
            for (int k = 0; k < P_; ++k) {
                d += sred[tid * P_ + k];
                s += sred[224 + tid * P_ + k];
            }
            const int n = ph * NW_ + tid;
            g_dot[(chunk * B_ + b) * N_ + n] = d;
            g_nsq[(chunk * B_ + b) * N_ + n] = s;
        }

        // ph==0 tiles also compute partial ||q||^2 (warp shuffle reduce)
        if (ph == 0) {
            float acc = 0.f;
            for (int idx = tid; idx < QSZ_; idx += 224) {
                float v = smq[idx];
                acc = fmaf(v, v, acc);
            }
#pragma unroll
            for (int o = 16; o > 0; o >>= 1)
                acc += __shfl_down_sync(0xffffffffu, acc, o);
            __syncthreads();               // sred readers above are done
            if ((tid & 31) == 0) sred[tid >> 5] = acc;
            __syncthreads();
            if (tid == 0) {
                float s = 0.f;
#pragma unroll
                for (int k = 0; k < 7; ++k) s += sred[k];
                g_qsq[chunk * B_ + b] = s;
            }
        }
    }
}

// ---------------------------------------------------------------------------
// Kernel 2: per-batch cosine-sim -> normalize -> log-softmax -> loss_b,
// with last-block mean into d_out (fused finalize; R8-validated form).
// ---------------------------------------------------------------------------
__global__ __launch_bounds__(256)
void finalize_kernel(const float* __restrict__ logit_scale,
                     const int*   __restrict__ gt,
                     float* __restrict__ out) {
    const int b   = blockIdx.x;
    const int tid = threadIdx.x;
    __shared__ float sh[256];
    __shared__ int   s_rank;

    // ||q||^2 = sum of chunk partials
    sh[tid] = (tid < NCH_) ? g_qsq[tid * B_ + b] : 0.f;
    __syncthreads();
    for (int s = 128; s > 0; s >>= 1) {
        if (tid < s) sh[tid] += sh[tid + s];
        __syncthreads();
    }
    const float Qc = fmaxf(sqrtf(sh[0]), EPS_COS);
    __syncthreads();

    // Per-patch (n == tid) sums across chunks
    const int n = tid;
    float dot = 0.f, tsq = 0.f;
#pragma unroll 8
    for (int ch = 0; ch < NCH_; ++ch) {
        dot += g_dot[(ch * B_ + b) * N_ + n];
        tsq += g_nsq[(ch * B_ + b) * N_ + n];
    }
    float s_n = dot / (fmaxf(sqrtf(tsq), EPS_COS) * Qc);

    // F.normalize over the 256-wide sim vector
    sh[tid] = s_n * s_n;
    __syncthreads();
    for (int s = 128; s > 0; s >>= 1) {
        if (tid < s) sh[tid] += sh[tid + s];
        __syncthreads();
    }
    const float r = fmaxf(sqrtf(sh[0]), EPS_NORM);
    __syncthreads();

    const float l = logit_scale[0] * (s_n / r);

    // log-softmax: max
    sh[tid] = l;
    __syncthreads();
    for (int s = 128; s > 0; s >>= 1) {
        if (tid < s) sh[tid] = fmaxf(sh[tid], sh[tid + s]);
        __syncthreads();
    }
    const float m = sh[0];
    __syncthreads();

    // sum exp
    sh[tid] = __expf(l - m);
    __syncthreads();
    for (int s = 128; s > 0; s >>= 1) {
        if (tid < s) sh[tid] += sh[tid + s];
        __syncthreads();
    }
    const float lse = m + logf(sh[0]);

    const int gx = gt[2 * b + 0];
    const int gy = gt[2 * b + 1];
    const int label = (gy / P_) * NW_ + (gx / P_);
    if (n == label) g_loss[b] = lse - l;   // -logp[label]

    // Last block computes the mean and resets scheduler state
    __syncthreads();
    __threadfence();
    if (tid == 0) s_rank = atomicAdd(&g_done, 1);
    __syncthreads();
    if (s_rank == B_ - 1 && tid == 0) {
        __threadfence();
        float acc = 0.f;
#pragma unroll
        for (int k = 0; k < B_; ++k) acc += g_loss[k];
        out[0]   = acc / (float)B_;
        g_ticket = 0;                      // reset for next graph replay
        g_done   = 0;
    }
}

// ---------------------------------------------------------------------------
extern "C" void kernel_launch(void* const* d_in, const int* in_sizes, int n_in,
                              void* d_out, int out_size) {
    const float* qf    = (const float*)d_in[0];   // query_feature [16,256,224,224]
    const float* rf    = (const float*)d_in[1];   // ref_feature   [16,256,224,224]
    const float* scale = (const float*)d_in[2];   // logit_scale scalar
    const int*   click = (const int*)  d_in[3];   // click_points [16,2] int32
    const int*   gt    = (const int*)  d_in[4];   // gt_points    [16,2] int32
    // d_in[5] = patch_size (14), fixed -> hardcoded

    accum_kernel<<<NCTA_, 224>>>(qf, rf, click);
    finalize_kernel<<<B_, 256>>>(scale, gt, (float*)d_out);
}